// round 5
// baseline (speedup 1.0000x reference)
#include <cuda_runtime.h>

#define NN   4096
#define IND  256
#define HID1 64
#define NH1  4
#define F1T  256
#define F2T  128

typedef unsigned long long u64;

// ---- scratch (device globals; no allocation allowed) ----
__device__ float g_Wh1[NN * F1T];
__device__ float g_h1 [NN * F1T];
__device__ float g_Wh2[NN * F2T];
__device__ float g_e1p_h[NH1 * NN], g_e1n_h[NH1 * NN];
__device__ float g_e2p_h[NH1 * NN], g_e2n_h[NH1 * NN];
__device__ float g_e1p_o[NN], g_e1n_o[NN], g_e2p_o[NN], g_e2n_o[NN];

// ---- packed fp32x2 helpers (sm_103a) ----
__device__ __forceinline__ u64 pack2(float lo, float hi) {
    return (u64)__float_as_uint(lo) | ((u64)__float_as_uint(hi) << 32);
}
__device__ __forceinline__ float lo2(u64 v) { return __uint_as_float((unsigned)v); }
__device__ __forceinline__ float hi2(u64 v) { return __uint_as_float((unsigned)(v >> 32)); }
__device__ __forceinline__ u64 fma2(u64 a, u64 b, u64 c) {
    u64 d;
    asm("fma.rn.f32x2 %0, %1, %2, %3;" : "=l"(d) : "l"(a), "l"(b), "l"(c));
    return d;
}

// ---- cp.async helpers ----
__device__ __forceinline__ unsigned sptr(const void* p) {
    return (unsigned)__cvta_generic_to_shared(p);
}
__device__ __forceinline__ void cp16(unsigned dst, const void* src) {
    asm volatile("cp.async.ca.shared.global [%0], [%1], 16;" :: "r"(dst), "l"(src) : "memory");
}
__device__ __forceinline__ void cp4(unsigned dst, const void* src) {
    asm volatile("cp.async.ca.shared.global [%0], [%1], 4;" :: "r"(dst), "l"(src) : "memory");
}
__device__ __forceinline__ void cp_commit() {
    asm volatile("cp.async.commit_group;" ::: "memory");
}
template <int N>
__device__ __forceinline__ void cp_wait() {
    asm volatile("cp.async.wait_group %0;" :: "n"(N) : "memory");
}

// =======================================================================
// GEMM: C[4096, FCOLS] = A[4096,256] @ B
// block = 32 rows x FCOLS, 512 threads, thread = 4 rows x FPT feats
// double-buffered cp.async tiles; inner loop pure LDS + FFMA2
// =======================================================================
template <int FCOLS, bool HEADS_B>
__device__ __forceinline__ void gemm_body(const float* __restrict__ A,
                                          const float* __restrict__ B,
                                          float* __restrict__ C) {
    constexpr int K = 256, XPAD = 36, FPT = FCOLS / 64;
    constexpr int NCB = 32 * FCOLS / 2048;       // 16B chunks/thread for B tile
    const int tid   = threadIdx.x;
    const int feat0 = (tid & 63) * FPT;
    const int r0    = (tid >> 6) * 4;
    const int row0  = blockIdx.x * 32;

    __shared__ __align__(16) float x_s[2][32 * XPAD];     // [kk][r]
    __shared__ __align__(16) float b_s[2][32 * FCOLS];    // [kk][feat]

    auto issue_tile = [&](int buf, int k0) {
#pragma unroll
        for (int i = 0; i < 2; i++) {            // x: transposed, 4B each
            int e = i * 512 + tid;
            int r = e & 31, kk = e >> 5;
            cp4(sptr(&x_s[buf][kk * XPAD + r]), &A[(row0 + r) * K + k0 + kk]);
        }
#pragma unroll
        for (int c = 0; c < NCB; c++) {          // B: flat 16B chunks
            int flat = c * 2048 + tid * 4;
            int kk = flat / FCOLS, feat = flat % FCOLS;
            const float* src = HEADS_B
                ? &B[(feat >> 6) * (IND * HID1) + (k0 + kk) * HID1 + (feat & 63)]
                : &B[(k0 + kk) * FCOLS + feat];
            cp16(sptr(&b_s[buf][flat]), src);
        }
        cp_commit();
    };

    u64 acc[FPT][2];
#pragma unroll
    for (int f = 0; f < FPT; f++) { acc[f][0] = 0ull; acc[f][1] = 0ull; }

    issue_tile(0, 0);
    for (int t = 0; t < K / 32; t++) {
        if (t + 1 < K / 32) { issue_tile((t + 1) & 1, (t + 1) * 32); cp_wait<1>(); }
        else                { cp_wait<0>(); }
        __syncthreads();
        const float* xs = x_s[t & 1];
        const float* bs = b_s[t & 1];
#pragma unroll 8
        for (int kk = 0; kk < 32; kk++) {
            ulonglong2 pv = *(const ulonglong2*)&xs[kk * XPAD + r0];
            float wv[FPT];
            if constexpr (FPT == 4) {
                float4 v = *(const float4*)&bs[kk * FCOLS + feat0];
                wv[0] = v.x; wv[1] = v.y; wv[2] = v.z; wv[3] = v.w;
            } else {
                float2 v = *(const float2*)&bs[kk * FCOLS + feat0];
                wv[0] = v.x; wv[1] = v.y;
            }
#pragma unroll
            for (int f = 0; f < FPT; f++) {
                u64 w2 = pack2(wv[f], wv[f]);
                acc[f][0] = fma2(pv.x, w2, acc[f][0]);
                acc[f][1] = fma2(pv.y, w2, acc[f][1]);
            }
        }
        __syncthreads();
    }
#pragma unroll
    for (int i = 0; i < 4; i++) {
        float v[FPT];
#pragma unroll
        for (int f = 0; f < FPT; f++)
            v[f] = (i & 1) ? hi2(acc[f][i >> 1]) : lo2(acc[f][i >> 1]);
        float* cp = &C[(row0 + r0 + i) * FCOLS + feat0];
        if constexpr (FPT == 4) *(float4*)cp = make_float4(v[0], v[1], v[2], v[3]);
        else                    *(float2*)cp = make_float2(v[0], v[1]);
    }
}

__global__ void __launch_bounds__(512) gemm1_k(const float* __restrict__ x,
                                               const float* __restrict__ W_heads) {
    gemm_body<F1T, true>(x, W_heads, g_Wh1);
}
__global__ void __launch_bounds__(512) gemm2_k(const float* __restrict__ W_out) {
    gemm_body<F2T, false>(g_h1, W_out, g_Wh2);
}

// =======================================================================
// f-vector kernels: f = Wh . a halves, then store factored-exp forms
// =======================================================================
__global__ void fvec1_k(const float* __restrict__ a_heads) {
    const int i = blockIdx.x;
    const int t = threadIdx.x;            // 0..63
    const int lane = t & 31, w = t >> 5;
    float p1[NH1], p2[NH1];
#pragma unroll
    for (int h = 0; h < NH1; h++) {
        float v = g_Wh1[i * F1T + h * HID1 + t];
        p1[h] = v * a_heads[h * (2 * HID1) + t];
        p2[h] = v * a_heads[h * (2 * HID1) + HID1 + t];
    }
#pragma unroll
    for (int off = 16; off; off >>= 1)
#pragma unroll
        for (int h = 0; h < NH1; h++) {
            p1[h] += __shfl_down_sync(0xffffffffu, p1[h], off);
            p2[h] += __shfl_down_sync(0xffffffffu, p2[h], off);
        }
    __shared__ float red[2][2 * NH1];
    if (lane == 0) {
#pragma unroll
        for (int h = 0; h < NH1; h++) { red[w][h] = p1[h]; red[w][NH1 + h] = p2[h]; }
    }
    __syncthreads();
    if (t == 0) {
#pragma unroll
        for (int h = 0; h < NH1; h++) {
            float f1 = red[0][h] + red[1][h];
            float f2 = red[0][NH1 + h] + red[1][NH1 + h];
            g_e1p_h[h * NN + i] = __expf(f1);
            g_e1n_h[h * NN + i] = __expf(0.5f * f1);
            g_e2p_h[h * NN + i] = __expf(f2);
            g_e2n_h[h * NN + i] = __expf(0.5f * f2);
        }
    }
}

__global__ void fvec2_k(const float* __restrict__ a_out) {
    const int i = blockIdx.x;
    const int t = threadIdx.x;            // 0..127
    const int lane = t & 31, w = t >> 5;
    float v  = g_Wh2[i * F2T + t];
    float p1 = v * a_out[t];
    float p2 = v * a_out[F2T + t];
#pragma unroll
    for (int off = 16; off; off >>= 1) {
        p1 += __shfl_down_sync(0xffffffffu, p1, off);
        p2 += __shfl_down_sync(0xffffffffu, p2, off);
    }
    __shared__ float red[4][2];
    if (lane == 0) { red[w][0] = p1; red[w][1] = p2; }
    __syncthreads();
    if (t == 0) {
        float f1 = red[0][0] + red[1][0] + red[2][0] + red[3][0];
        float f2 = red[0][1] + red[1][1] + red[2][1] + red[3][1];
        g_e1p_o[i] = __expf(f1);
        g_e1n_o[i] = __expf(0.5f * f1);
        g_e2p_o[i] = __expf(f2);
        g_e2n_o[i] = __expf(0.5f * f2);
    }
}

// =======================================================================
// Fused attention: block = 32 rows x F_TOT, 512 threads, 32-wide j-tiles
// Wh tile double-buffered in smem via cp.async; p tile in smem.
// thread = 4 rows x FPT feats in accumulate: 2 LDS.128 -> 2*FPT FFMA2
// p = mask * max(e1p[i]*e2p[j], e1n[i]*e2n[j])   (== mask*exp(leakyrelu))
// =======================================================================
template <int F_TOT, int NH>
__device__ __forceinline__ void attn_body(const int* __restrict__ adj,
                                          const float* __restrict__ Wh,
                                          const float* __restrict__ e1p,
                                          const float* __restrict__ e1n,
                                          const float* __restrict__ e2p,
                                          const float* __restrict__ e2n,
                                          float* __restrict__ out) {
    constexpr int TI = 32, TJ = 32, PPAD = 36;
    constexpr int FPT = F_TOT / 64;
    constexpr int HID = F_TOT / NH;
    constexpr int NTILES = NN / TJ;
    constexpr int NCW = TJ * F_TOT / 2048;       // 16B chunks/thread per Wh tile
    const int tid   = threadIdx.x;
    const int lane  = tid & 31, warp = tid >> 5;
    const int row0  = blockIdx.x * TI;
    const int feat0 = (tid & 63) * FPT;
    const int r0    = (tid >> 6) * 4;
    const int hh    = feat0 / HID;

    __shared__ __align__(16) float p_s[NH * TJ * PPAD];      // [h][jj][r]
    __shared__ __align__(16) float wh_s[2][TJ * F_TOT];      // [jj][feat]
    __shared__ float denom_s[TI * NH];

    auto issue_wh = [&](int buf, int j0) {
#pragma unroll
        for (int c = 0; c < NCW; c++) {
            int flat = c * 2048 + tid * 4;
            cp16(sptr(&wh_s[buf][flat]), &Wh[j0 * F_TOT + flat]);
        }
        cp_commit();
    };

    u64 acc[FPT][2];
#pragma unroll
    for (int f = 0; f < FPT; f++) { acc[f][0] = 0ull; acc[f][1] = 0ull; }

    float dpart[2][NH];
#pragma unroll
    for (int q = 0; q < 2; q++)
#pragma unroll
        for (int h = 0; h < NH; h++) dpart[q][h] = 0.0f;

    float E1p[2][NH], E1n[2][NH];
#pragma unroll
    for (int q = 0; q < 2; q++)
#pragma unroll
        for (int h = 0; h < NH; h++) {
            E1p[q][h] = e1p[h * NN + row0 + q * 16 + warp];
            E1n[q][h] = e1n[h * NN + row0 + q * 16 + warp];
        }

    // prefetch tile-0 j-side factors + mask (registers), issue tile-0 Wh copy
    float E2pc[NH], E2nc[NH];
    int mc[2];
#pragma unroll
    for (int h = 0; h < NH; h++) {
        E2pc[h] = e2p[h * NN + lane];
        E2nc[h] = e2n[h * NN + lane];
    }
#pragma unroll
    for (int q = 0; q < 2; q++)
        mc[q] = adj[(row0 + q * 16 + warp) * NN + lane];
    issue_wh(0, 0);

    for (int t = 0; t < NTILES; t++) {
        // ---- p phase: thread handles (jj = lane, r = q*16 + warp) ----
#pragma unroll
        for (int q = 0; q < 2; q++) {
            const int r = q * 16 + warp;
#pragma unroll
            for (int h = 0; h < NH; h++) {
                float pa = E1p[q][h] * E2pc[h];
                float pb = E1n[q][h] * E2nc[h];
                float p  = (mc[q] > 0) ? fmaxf(pa, pb) : 0.0f;
                p_s[(h * TJ + lane) * PPAD + r] = p;
                dpart[q][h] += p;
            }
        }
        // prefetch next tile's j-side regs + issue next Wh copy
        if (t + 1 < NTILES) {
            const int j0n = (t + 1) * TJ;
#pragma unroll
            for (int h = 0; h < NH; h++) {
                E2pc[h] = e2p[h * NN + j0n + lane];
                E2nc[h] = e2n[h * NN + j0n + lane];
            }
#pragma unroll
            for (int q = 0; q < 2; q++)
                mc[q] = adj[(row0 + q * 16 + warp) * NN + j0n + lane];
            issue_wh((t + 1) & 1, j0n);
            cp_wait<1>();
        } else {
            cp_wait<0>();
        }
        __syncthreads();
        // ---- accumulate: 2 LDS.128 -> 2*FPT FFMA2 per jj ----
        const float* ws = wh_s[t & 1];
#pragma unroll 8
        for (int jj = 0; jj < TJ; jj++) {
            ulonglong2 pv = *(const ulonglong2*)&p_s[(hh * TJ + jj) * PPAD + r0];
            float wv[FPT];
            if constexpr (FPT == 4) {
                float4 v = *(const float4*)&ws[jj * F_TOT + feat0];
                wv[0] = v.x; wv[1] = v.y; wv[2] = v.z; wv[3] = v.w;
            } else {
                float2 v = *(const float2*)&ws[jj * F_TOT + feat0];
                wv[0] = v.x; wv[1] = v.y;
            }
#pragma unroll
            for (int f = 0; f < FPT; f++) {
                u64 w2 = pack2(wv[f], wv[f]);
                acc[f][0] = fma2(pv.x, w2, acc[f][0]);
                acc[f][1] = fma2(pv.y, w2, acc[f][1]);
            }
        }
        __syncthreads();
    }

    // ---- denominator: warp-reduce over jj (= lanes) ----
#pragma unroll
    for (int q = 0; q < 2; q++)
#pragma unroll
        for (int h = 0; h < NH; h++) {
            float v = dpart[q][h];
#pragma unroll
            for (int off = 16; off; off >>= 1)
                v += __shfl_down_sync(0xffffffffu, v, off);
            if (lane == 0) denom_s[(q * 16 + warp) * NH + h] = v;
        }
    __syncthreads();

    // ---- normalize + ELU + vectorized store ----
    float inv[4];
#pragma unroll
    for (int i = 0; i < 4; i++)
        inv[i] = 1.0f / denom_s[(r0 + i) * NH + hh];
#pragma unroll
    for (int i = 0; i < 4; i++) {
        float v[FPT];
#pragma unroll
        for (int f = 0; f < FPT; f++) {
            float raw = (i & 1) ? hi2(acc[f][i >> 1]) : lo2(acc[f][i >> 1]);
            float x = raw * inv[i];
            v[f] = x > 0.0f ? x : expm1f(x);
        }
        float* op = &out[(row0 + r0 + i) * F_TOT + feat0];
        if constexpr (FPT == 4) *(float4*)op = make_float4(v[0], v[1], v[2], v[3]);
        else                    *(float2*)op = make_float2(v[0], v[1]);
    }
}

__global__ void __launch_bounds__(512) attn1_k(const int* __restrict__ adj) {
    attn_body<F1T, NH1>(adj, g_Wh1, g_e1p_h, g_e1n_h, g_e2p_h, g_e2n_h, g_h1);
}
__global__ void __launch_bounds__(512) attn2_k(const int* __restrict__ adj,
                                               float* __restrict__ out) {
    attn_body<F2T, 1>(adj, g_Wh2, g_e1p_o, g_e1n_o, g_e2p_o, g_e2n_o, out);
}

// =======================================================================
extern "C" void kernel_launch(void* const* d_in, const int* in_sizes, int n_in,
                              void* d_out, int out_size) {
    const float* x       = (const float*)d_in[0];
    const int*   adj     = (const int*)  d_in[1];
    const float* W_heads = (const float*)d_in[2];
    const float* a_heads = (const float*)d_in[3];
    const float* W_out   = (const float*)d_in[4];
    const float* a_out   = (const float*)d_in[5];
    float* out = (float*)d_out;

    gemm1_k<<<NN / 32, 512>>>(x, W_heads);
    fvec1_k<<<NN, 64>>>(a_heads);
    attn1_k<<<NN / 32, 512>>>(adj);
    gemm2_k<<<NN / 32, 512>>>(W_out);
    fvec2_k<<<NN, 128>>>(a_out);
    attn2_k<<<NN / 32, 512>>>(adj, out);
}

// round 6
// speedup vs baseline: 1.5304x; 1.5304x over previous
#include <cuda_runtime.h>

#define NN   4096
#define IND  256
#define HID1 64
#define NH1  4
#define F1T  256
#define F2T  128

typedef unsigned long long u64;

// ---- scratch (device globals; no allocation allowed) ----
__device__ float g_Wh1[NN * F1T];
__device__ float g_h1 [NN * F1T];
__device__ float g_Wh2[NN * F2T];
__device__ float g_e1p_h[NH1 * NN], g_e1n_h[NH1 * NN];
__device__ float g_e2p_h[NH1 * NN], g_e2n_h[NH1 * NN];
__device__ float g_e1p_o[NN], g_e1n_o[NN], g_e2p_o[NN], g_e2n_o[NN];

// ---- packed fp32x2 helpers (sm_103a) ----
__device__ __forceinline__ u64 pack2(float lo, float hi) {
    return (u64)__float_as_uint(lo) | ((u64)__float_as_uint(hi) << 32);
}
__device__ __forceinline__ float lo2(u64 v) { return __uint_as_float((unsigned)v); }
__device__ __forceinline__ float hi2(u64 v) { return __uint_as_float((unsigned)(v >> 32)); }
__device__ __forceinline__ u64 fma2(u64 a, u64 b, u64 c) {
    u64 d;
    asm("fma.rn.f32x2 %0, %1, %2, %3;" : "=l"(d) : "l"(a), "l"(b), "l"(c));
    return d;
}

// ---- cp.async helpers ----
__device__ __forceinline__ unsigned sptr(const void* p) {
    return (unsigned)__cvta_generic_to_shared(p);
}
__device__ __forceinline__ void cp16(unsigned dst, const void* src) {
    asm volatile("cp.async.ca.shared.global [%0], [%1], 16;" :: "r"(dst), "l"(src) : "memory");
}
__device__ __forceinline__ void cp4(unsigned dst, const void* src) {
    asm volatile("cp.async.ca.shared.global [%0], [%1], 4;" :: "r"(dst), "l"(src) : "memory");
}
__device__ __forceinline__ void cp_commit() {
    asm volatile("cp.async.commit_group;" ::: "memory");
}
template <int N>
__device__ __forceinline__ void cp_wait() {
    asm volatile("cp.async.wait_group %0;" :: "n"(N) : "memory");
}

// =======================================================================
// GEMM: C[4096, FCOLS] = A[4096,256] @ B
// block = 32 rows x FCOLS, 512 threads, thread = 4 rows x FPT feats
// double-buffered cp.async tiles; inner loop pure LDS + FFMA2
// =======================================================================
template <int FCOLS, bool HEADS_B>
__device__ __forceinline__ void gemm_body(const float* __restrict__ A,
                                          const float* __restrict__ B,
                                          float* __restrict__ C) {
    constexpr int K = 256, XPAD = 36, FPT = FCOLS / 64;
    constexpr int NCB = 32 * FCOLS / 2048;       // 16B chunks/thread for B tile
    const int tid   = threadIdx.x;
    const int feat0 = (tid & 63) * FPT;
    const int r0    = (tid >> 6) * 4;
    const int row0  = blockIdx.x * 32;

    __shared__ __align__(16) float x_s[2][32 * XPAD];     // [kk][r]
    __shared__ __align__(16) float b_s[2][32 * FCOLS];    // [kk][feat]

    auto issue_tile = [&](int buf, int k0) {
#pragma unroll
        for (int i = 0; i < 2; i++) {            // x: transposed, 4B each
            int e = i * 512 + tid;
            int r = e & 31, kk = e >> 5;
            cp4(sptr(&x_s[buf][kk * XPAD + r]), &A[(row0 + r) * K + k0 + kk]);
        }
#pragma unroll
        for (int c = 0; c < NCB; c++) {          // B: flat 16B chunks
            int flat = c * 2048 + tid * 4;
            int kk = flat / FCOLS, feat = flat % FCOLS;
            const float* src = HEADS_B
                ? &B[(feat >> 6) * (IND * HID1) + (k0 + kk) * HID1 + (feat & 63)]
                : &B[(k0 + kk) * FCOLS + feat];
            cp16(sptr(&b_s[buf][flat]), src);
        }
        cp_commit();
    };

    u64 acc[FPT][2];
#pragma unroll
    for (int f = 0; f < FPT; f++) { acc[f][0] = 0ull; acc[f][1] = 0ull; }

    issue_tile(0, 0);
    for (int t = 0; t < K / 32; t++) {
        if (t + 1 < K / 32) { issue_tile((t + 1) & 1, (t + 1) * 32); cp_wait<1>(); }
        else                { cp_wait<0>(); }
        __syncthreads();
        const float* xs = x_s[t & 1];
        const float* bs = b_s[t & 1];
#pragma unroll 8
        for (int kk = 0; kk < 32; kk++) {
            ulonglong2 pv = *(const ulonglong2*)&xs[kk * XPAD + r0];
            float wv[FPT];
            if constexpr (FPT == 4) {
                float4 v = *(const float4*)&bs[kk * FCOLS + feat0];
                wv[0] = v.x; wv[1] = v.y; wv[2] = v.z; wv[3] = v.w;
            } else {
                float2 v = *(const float2*)&bs[kk * FCOLS + feat0];
                wv[0] = v.x; wv[1] = v.y;
            }
#pragma unroll
            for (int f = 0; f < FPT; f++) {
                u64 w2 = pack2(wv[f], wv[f]);
                acc[f][0] = fma2(pv.x, w2, acc[f][0]);
                acc[f][1] = fma2(pv.y, w2, acc[f][1]);
            }
        }
        __syncthreads();
    }
#pragma unroll
    for (int i = 0; i < 4; i++) {
        float v[FPT];
#pragma unroll
        for (int f = 0; f < FPT; f++)
            v[f] = (i & 1) ? hi2(acc[f][i >> 1]) : lo2(acc[f][i >> 1]);
        float* cp = &C[(row0 + r0 + i) * FCOLS + feat0];
        if constexpr (FPT == 4) *(float4*)cp = make_float4(v[0], v[1], v[2], v[3]);
        else                    *(float2*)cp = make_float2(v[0], v[1]);
    }
}

__global__ void __launch_bounds__(512, 1) gemm1_k(const float* __restrict__ x,
                                                  const float* __restrict__ W_heads) {
    gemm_body<F1T, true>(x, W_heads, g_Wh1);
}
__global__ void __launch_bounds__(512, 1) gemm2_k(const float* __restrict__ W_out) {
    gemm_body<F2T, false>(g_h1, W_out, g_Wh2);
}

// =======================================================================
// f-vector kernels: f = Wh . a halves, then store factored-exp forms
// =======================================================================
__global__ void fvec1_k(const float* __restrict__ a_heads) {
    const int i = blockIdx.x;
    const int t = threadIdx.x;            // 0..63
    const int lane = t & 31, w = t >> 5;
    float p1[NH1], p2[NH1];
#pragma unroll
    for (int h = 0; h < NH1; h++) {
        float v = g_Wh1[i * F1T + h * HID1 + t];
        p1[h] = v * a_heads[h * (2 * HID1) + t];
        p2[h] = v * a_heads[h * (2 * HID1) + HID1 + t];
    }
#pragma unroll
    for (int off = 16; off; off >>= 1)
#pragma unroll
        for (int h = 0; h < NH1; h++) {
            p1[h] += __shfl_down_sync(0xffffffffu, p1[h], off);
            p2[h] += __shfl_down_sync(0xffffffffu, p2[h], off);
        }
    __shared__ float red[2][2 * NH1];
    if (lane == 0) {
#pragma unroll
        for (int h = 0; h < NH1; h++) { red[w][h] = p1[h]; red[w][NH1 + h] = p2[h]; }
    }
    __syncthreads();
    if (t == 0) {
#pragma unroll
        for (int h = 0; h < NH1; h++) {
            float f1 = red[0][h] + red[1][h];
            float f2 = red[0][NH1 + h] + red[1][NH1 + h];
            g_e1p_h[h * NN + i] = __expf(f1);
            g_e1n_h[h * NN + i] = __expf(0.5f * f1);
            g_e2p_h[h * NN + i] = __expf(f2);
            g_e2n_h[h * NN + i] = __expf(0.5f * f2);
        }
    }
}

__global__ void fvec2_k(const float* __restrict__ a_out) {
    const int i = blockIdx.x;
    const int t = threadIdx.x;            // 0..127
    const int lane = t & 31, w = t >> 5;
    float v  = g_Wh2[i * F2T + t];
    float p1 = v * a_out[t];
    float p2 = v * a_out[F2T + t];
#pragma unroll
    for (int off = 16; off; off >>= 1) {
        p1 += __shfl_down_sync(0xffffffffu, p1, off);
        p2 += __shfl_down_sync(0xffffffffu, p2, off);
    }
    __shared__ float red[4][2];
    if (lane == 0) { red[w][0] = p1; red[w][1] = p2; }
    __syncthreads();
    if (t == 0) {
        float f1 = red[0][0] + red[1][0] + red[2][0] + red[3][0];
        float f2 = red[0][1] + red[1][1] + red[2][1] + red[3][1];
        g_e1p_o[i] = __expf(f1);
        g_e1n_o[i] = __expf(0.5f * f1);
        g_e2p_o[i] = __expf(f2);
        g_e2n_o[i] = __expf(0.5f * f2);
    }
}

// =======================================================================
// Fused attention: block = 32 rows x F_TOT, 512 threads, 32-wide j-tiles
// Wh tile double-buffered in smem via cp.async; p tile in smem.
// thread = 4 rows x FPT feats in accumulate: 2 LDS.128 -> 2*FPT FFMA2
// p = mask * max(e1p[i]*e2p[j], e1n[i]*e2n[j])   (== mask*exp(leakyrelu))
// =======================================================================
template <int F_TOT, int NH>
__device__ __forceinline__ void attn_body(const int* __restrict__ adj,
                                          const float* __restrict__ Wh,
                                          const float* __restrict__ e1p,
                                          const float* __restrict__ e1n,
                                          const float* __restrict__ e2p,
                                          const float* __restrict__ e2n,
                                          float* __restrict__ out) {
    constexpr int TI = 32, TJ = 32, PPAD = 36;
    constexpr int FPT = F_TOT / 64;
    constexpr int HID = F_TOT / NH;
    constexpr int NTILES = NN / TJ;
    constexpr int NCW = TJ * F_TOT / 2048;       // 16B chunks/thread per Wh tile
    const int tid   = threadIdx.x;
    const int lane  = tid & 31, warp = tid >> 5;
    const int row0  = blockIdx.x * TI;
    const int feat0 = (tid & 63) * FPT;
    const int r0    = (tid >> 6) * 4;
    const int hh    = feat0 / HID;

    __shared__ __align__(16) float p_s[NH * TJ * PPAD];      // [h][jj][r]
    __shared__ __align__(16) float wh_s[2][TJ * F_TOT];      // [jj][feat]
    __shared__ float denom_s[TI * NH];

    auto issue_wh = [&](int buf, int j0) {
#pragma unroll
        for (int c = 0; c < NCW; c++) {
            int flat = c * 2048 + tid * 4;
            cp16(sptr(&wh_s[buf][flat]), &Wh[j0 * F_TOT + flat]);
        }
        cp_commit();
    };

    u64 acc[FPT][2];
#pragma unroll
    for (int f = 0; f < FPT; f++) { acc[f][0] = 0ull; acc[f][1] = 0ull; }

    float dpart[2][NH];
#pragma unroll
    for (int q = 0; q < 2; q++)
#pragma unroll
        for (int h = 0; h < NH; h++) dpart[q][h] = 0.0f;

    float E1p[2][NH], E1n[2][NH];
#pragma unroll
    for (int q = 0; q < 2; q++)
#pragma unroll
        for (int h = 0; h < NH; h++) {
            E1p[q][h] = e1p[h * NN + row0 + q * 16 + warp];
            E1n[q][h] = e1n[h * NN + row0 + q * 16 + warp];
        }

    // prefetch tile-0 j-side factors + mask (registers), issue tile-0 Wh copy
    float E2pc[NH], E2nc[NH];
    int mc[2];
#pragma unroll
    for (int h = 0; h < NH; h++) {
        E2pc[h] = e2p[h * NN + lane];
        E2nc[h] = e2n[h * NN + lane];
    }
#pragma unroll
    for (int q = 0; q < 2; q++)
        mc[q] = adj[(row0 + q * 16 + warp) * NN + lane];
    issue_wh(0, 0);

    for (int t = 0; t < NTILES; t++) {
        // ---- p phase: thread handles (jj = lane, r = q*16 + warp) ----
#pragma unroll
        for (int q = 0; q < 2; q++) {
            const int r = q * 16 + warp;
#pragma unroll
            for (int h = 0; h < NH; h++) {
                float pa = E1p[q][h] * E2pc[h];
                float pb = E1n[q][h] * E2nc[h];
                float p  = (mc[q] > 0) ? fmaxf(pa, pb) : 0.0f;
                p_s[(h * TJ + lane) * PPAD + r] = p;
                dpart[q][h] += p;
            }
        }
        // prefetch next tile's j-side regs + issue next Wh copy
        if (t + 1 < NTILES) {
            const int j0n = (t + 1) * TJ;
#pragma unroll
            for (int h = 0; h < NH; h++) {
                E2pc[h] = e2p[h * NN + j0n + lane];
                E2nc[h] = e2n[h * NN + j0n + lane];
            }
#pragma unroll
            for (int q = 0; q < 2; q++)
                mc[q] = adj[(row0 + q * 16 + warp) * NN + j0n + lane];
            issue_wh((t + 1) & 1, j0n);
            cp_wait<1>();
        } else {
            cp_wait<0>();
        }
        __syncthreads();
        // ---- accumulate: 2 LDS.128 -> 2*FPT FFMA2 per jj ----
        const float* ws = wh_s[t & 1];
#pragma unroll 8
        for (int jj = 0; jj < TJ; jj++) {
            ulonglong2 pv = *(const ulonglong2*)&p_s[(hh * TJ + jj) * PPAD + r0];
            float wv[FPT];
            if constexpr (FPT == 4) {
                float4 v = *(const float4*)&ws[jj * F_TOT + feat0];
                wv[0] = v.x; wv[1] = v.y; wv[2] = v.z; wv[3] = v.w;
            } else {
                float2 v = *(const float2*)&ws[jj * F_TOT + feat0];
                wv[0] = v.x; wv[1] = v.y;
            }
#pragma unroll
            for (int f = 0; f < FPT; f++) {
                u64 w2 = pack2(wv[f], wv[f]);
                acc[f][0] = fma2(pv.x, w2, acc[f][0]);
                acc[f][1] = fma2(pv.y, w2, acc[f][1]);
            }
        }
        __syncthreads();
    }

    // ---- denominator: warp-reduce over jj (= lanes) ----
#pragma unroll
    for (int q = 0; q < 2; q++)
#pragma unroll
        for (int h = 0; h < NH; h++) {
            float v = dpart[q][h];
#pragma unroll
            for (int off = 16; off; off >>= 1)
                v += __shfl_down_sync(0xffffffffu, v, off);
            if (lane == 0) denom_s[(q * 16 + warp) * NH + h] = v;
        }
    __syncthreads();

    // ---- normalize + ELU + vectorized store ----
    float inv[4];
#pragma unroll
    for (int i = 0; i < 4; i++)
        inv[i] = 1.0f / denom_s[(r0 + i) * NH + hh];
#pragma unroll
    for (int i = 0; i < 4; i++) {
        float v[FPT];
#pragma unroll
        for (int f = 0; f < FPT; f++) {
            float raw = (i & 1) ? hi2(acc[f][i >> 1]) : lo2(acc[f][i >> 1]);
            float x = raw * inv[i];
            v[f] = x > 0.0f ? x : expm1f(x);
        }
        float* op = &out[(row0 + r0 + i) * F_TOT + feat0];
        if constexpr (FPT == 4) *(float4*)op = make_float4(v[0], v[1], v[2], v[3]);
        else                    *(float2*)op = make_float2(v[0], v[1]);
    }
}

__global__ void __launch_bounds__(512, 1) attn1_k(const int* __restrict__ adj) {
    attn_body<F1T, NH1>(adj, g_Wh1, g_e1p_h, g_e1n_h, g_e2p_h, g_e2n_h, g_h1);
}
__global__ void __launch_bounds__(512, 1) attn2_k(const int* __restrict__ adj,
                                                  float* __restrict__ out) {
    attn_body<F2T, 1>(adj, g_Wh2, g_e1p_o, g_e1n_o, g_e2p_o, g_e2n_o, out);
}

// =======================================================================
extern "C" void kernel_launch(void* const* d_in, const int* in_sizes, int n_in,
                              void* d_out, int out_size) {
    const float* x       = (const float*)d_in[0];
    const int*   adj     = (const int*)  d_in[1];
    const float* W_heads = (const float*)d_in[2];
    const float* a_heads = (const float*)d_in[3];
    const float* W_out   = (const float*)d_in[4];
    const float* a_out   = (const float*)d_in[5];
    float* out = (float*)d_out;

    gemm1_k<<<NN / 32, 512>>>(x, W_heads);
    fvec1_k<<<NN, 64>>>(a_heads);
    attn1_k<<<NN / 32, 512>>>(adj);
    gemm2_k<<<NN / 32, 512>>>(W_out);
    fvec2_k<<<NN, 128>>>(a_out);
    attn2_k<<<NN / 32, 512>>>(adj, out);
}